// round 3
// baseline (speedup 1.0000x reference)
#include <cuda_runtime.h>
#include <cstdint>

// DeepMapping2D occupancy_generation, GB300 sm_103a.  Round 3.
//
//   output[b] = K_b ones then zeros, K_b = #bins with count >= 53.
//   Min-shift is a bin bijection -> K_b shift-invariant -> no min pass.
//
// R3: hist kernel is at the REDG LSU issue floor (~1.29 cyc/lane/SM ~= 81us);
// squeeze the auxiliary ~29us instead:
//   * zero kernel removed: the count pass re-zeroes g_hist as it reads it
//     (device globals start zeroed; every launch restores the invariant).
//   * out kernel fused into the count pass via a last-CTA-per-batch ticket.
//   -> 2 launches total.

#define NBATCH  64
#define NPTS    262144
#define TOPK    5120
#define GZ_LOG2 10
#define BINS_PER_BATCH (1024u * 1024u)                 // 1M u8 bins / batch
#define HWORDS_PER_BATCH (BINS_PER_BATCH / 4)          // 256K u32 / batch
#define CNT_BLOCKS_PER_BATCH 64

__device__ unsigned int g_hist[(size_t)NBATCH * HWORDS_PER_BATCH];  // 64 MB, load-zeroed
__device__ unsigned int g_count[NBATCH];                            // load-zeroed
__device__ unsigned int g_done[NBATCH];                             // load-zeroed

// ---------------------------------------------------------------------------
// Kernel 1: histogram scatter, RED-only inner loop (REDG.E byte-packed adds).
// grid = (64 x-blocks, 64 batches) x 256 thr; 16 points/thread.
// ---------------------------------------------------------------------------
__global__ void dm2d_hist_kernel(const float4* __restrict__ pcd) {
    const int b = blockIdx.y;
    unsigned int* __restrict__ hist = g_hist + (size_t)b * HWORDS_PER_BATCH;
    const float4* __restrict__ base = pcd + (size_t)b * (NPTS / 2);

    const int tid    = blockIdx.x * blockDim.x + threadIdx.x;
    const int stride = gridDim.x * blockDim.x;

    #pragma unroll 4
    for (int i = tid; i < NPTS / 2; i += stride) {
        float4 p = __ldcs(&base[i]);   // two points: (x0,z0,x1,z1)

        // jnp.round = round-half-to-even == rintf under default RN mode.
        unsigned x0 = (unsigned)(int)rintf(1000.0f * p.x);
        unsigned z0 = (unsigned)(int)rintf(1000.0f * p.y);
        unsigned x1 = (unsigned)(int)rintf(1000.0f * p.z);
        unsigned z1 = (unsigned)(int)rintf(1000.0f * p.w);

        unsigned i0 = (x0 << GZ_LOG2) | z0;
        unsigned i1 = (x1 << GZ_LOG2) | z1;

        // fire-and-forget byte increments (return unused -> REDG)
        atomicAdd(&hist[i0 >> 2], 1u << ((i0 & 3u) << 3));
        atomicAdd(&hist[i1 >> 2], 1u << ((i1 & 3u) << 3));
    }
}

// ---------------------------------------------------------------------------
// Kernel 2 (fused): count bins >= 53, re-zero the histogram for the next
// launch, and let the last CTA per batch expand K_b into the output and
// reset the batch counters.
// grid = (64, 64) x 256 thr; each thread handles 4 uint4 = 64 bins.
// ---------------------------------------------------------------------------
__global__ void dm2d_count_out_kernel(float* __restrict__ out) {
    const int b = blockIdx.y;
    uint4* __restrict__ hist4 =
        reinterpret_cast<uint4*>(g_hist + (size_t)b * HWORDS_PER_BATCH);

    const int per_batch_u4 = BINS_PER_BATCH / 16;      // 65536 uint4 per batch
    const int tid    = blockIdx.x * blockDim.x + threadIdx.x;
    const int stride = gridDim.x * blockDim.x;         // 16384 threads

    unsigned int cnt = 0;
    const uint4 zero4 = make_uint4(0u, 0u, 0u, 0u);
    #pragma unroll 4
    for (int j = tid; j < per_batch_u4; j += stride) {
        uint4 w = hist4[j];
        hist4[j] = zero4;                              // restore invariant
        cnt += __popc(__vcmpgeu4(w.x, 0x35353535u) & 0x01010101u);
        cnt += __popc(__vcmpgeu4(w.y, 0x35353535u) & 0x01010101u);
        cnt += __popc(__vcmpgeu4(w.z, 0x35353535u) & 0x01010101u);
        cnt += __popc(__vcmpgeu4(w.w, 0x35353535u) & 0x01010101u);
    }

    // block reduce
    __shared__ unsigned int s_warp[8];
    #pragma unroll
    for (int off = 16; off > 0; off >>= 1)
        cnt += __shfl_down_sync(0xFFFFFFFFu, cnt, off);
    if ((threadIdx.x & 31) == 0) s_warp[threadIdx.x >> 5] = cnt;
    __syncthreads();

    __shared__ unsigned int s_ticket;
    if (threadIdx.x == 0) {
        unsigned int total = 0;
        #pragma unroll
        for (int w = 0; w < 8; w++) total += s_warp[w];
        if (total) atomicAdd(&g_count[b], total);
        __threadfence();                               // release g_count update
        s_ticket = atomicAdd(&g_done[b], 1u);
    }
    __syncthreads();

    if (s_ticket == CNT_BLOCKS_PER_BATCH - 1) {
        __threadfence();                               // acquire all g_count adds
        unsigned int K = *(volatile unsigned int*)&g_count[b];
        float* ob = out + (size_t)b * TOPK;
        for (int i = threadIdx.x; i < TOPK; i += blockDim.x)
            ob[i] = (i < (int)K) ? 1.0f : 0.0f;
        if (threadIdx.x == 0) {                        // reset for next launch
            g_count[b] = 0u;
            g_done[b]  = 0u;
        }
    }
}

extern "C" void kernel_launch(void* const* d_in, const int* in_sizes, int n_in,
                              void* d_out, int out_size) {
    (void)in_sizes; (void)n_in; (void)out_size;
    const float4* pcd = reinterpret_cast<const float4*>(d_in[0]);
    float* out = reinterpret_cast<float*>(d_out);

    dim3 hgrid(64, NBATCH);
    dm2d_hist_kernel<<<hgrid, 256>>>(pcd);

    dim3 cgrid(CNT_BLOCKS_PER_BATCH, NBATCH);
    dm2d_count_out_kernel<<<cgrid, 256>>>(out);
}

// round 4
// speedup vs baseline: 1.1284x; 1.1284x over previous
#include <cuda_runtime.h>
#include <cstdint>

// DeepMapping2D occupancy_generation, GB300 sm_103a.  Round 4.
//
//   output[b] = K_b ones then zeros, K_b = #bins with count >= 53.
//   Min-shift is a bin bijection -> K_b shift-invariant -> no min pass.
//
// R4, after the R3 fence disaster (grid-wide MEMBAR.GPU behind in-flight
// store queues -> 230us of barrier stall):
//   * count pass still re-zeroes the histogram as it reads it (saves the
//     10us standalone zero kernel), but with PLAIN stores -- visibility for
//     the next replay is guaranteed by kernel-launch boundaries, no fence.
//   * no tickets: output expansion is its own trivial kernel, one CTA per
//     batch, which also resets g_count (intra-block coordination only).

#define NBATCH  64
#define NPTS    262144
#define TOPK    5120
#define GZ_LOG2 10
#define BINS_PER_BATCH (1024u * 1024u)                 // 1M u8 bins / batch
#define HWORDS_PER_BATCH (BINS_PER_BATCH / 4)          // 256K u32 / batch

__device__ unsigned int g_hist[(size_t)NBATCH * HWORDS_PER_BATCH];  // 64 MB, load-zeroed
__device__ unsigned int g_count[NBATCH];                            // load-zeroed

// ---------------------------------------------------------------------------
// Kernel 1: histogram scatter, RED-only inner loop (REDG byte-packed adds).
// grid = (64 x-blocks, 64 batches) x 256 thr; 16 points/thread.
// At the REDG LSU issue floor (~1.29 cyc/lane): ~90us.
// ---------------------------------------------------------------------------
__global__ void dm2d_hist_kernel(const float4* __restrict__ pcd) {
    const int b = blockIdx.y;
    unsigned int* __restrict__ hist = g_hist + (size_t)b * HWORDS_PER_BATCH;
    const float4* __restrict__ base = pcd + (size_t)b * (NPTS / 2);

    const int tid    = blockIdx.x * blockDim.x + threadIdx.x;
    const int stride = gridDim.x * blockDim.x;

    #pragma unroll 4
    for (int i = tid; i < NPTS / 2; i += stride) {
        float4 p = __ldcs(&base[i]);   // two points: (x0,z0,x1,z1)

        // jnp.round = round-half-to-even == rintf under default RN mode.
        unsigned x0 = (unsigned)(int)rintf(1000.0f * p.x);
        unsigned z0 = (unsigned)(int)rintf(1000.0f * p.y);
        unsigned x1 = (unsigned)(int)rintf(1000.0f * p.z);
        unsigned z1 = (unsigned)(int)rintf(1000.0f * p.w);

        unsigned i0 = (x0 << GZ_LOG2) | z0;
        unsigned i1 = (x1 << GZ_LOG2) | z1;

        // fire-and-forget byte increments (return unused -> REDG)
        atomicAdd(&hist[i0 >> 2], 1u << ((i0 & 3u) << 3));
        atomicAdd(&hist[i1 >> 2], 1u << ((i1 & 3u) << 3));
    }
}

// ---------------------------------------------------------------------------
// Kernel 2: count bins >= 53 AND re-zero the histogram (plain stores, no
// fences -- kernel boundary orders them before the next replay's hist).
// grid = (64, 64) x 256 thr; each thread handles 4 uint4 = 64 bins.
// ---------------------------------------------------------------------------
__global__ void dm2d_count_kernel() {
    const int b = blockIdx.y;
    uint4* __restrict__ hist4 =
        reinterpret_cast<uint4*>(g_hist + (size_t)b * HWORDS_PER_BATCH);

    const int per_batch_u4 = BINS_PER_BATCH / 16;      // 65536 uint4 per batch
    const int tid    = blockIdx.x * blockDim.x + threadIdx.x;
    const int stride = gridDim.x * blockDim.x;         // 16384 threads

    unsigned int cnt = 0;
    const uint4 zero4 = make_uint4(0u, 0u, 0u, 0u);
    #pragma unroll 4
    for (int j = tid; j < per_batch_u4; j += stride) {
        uint4 w = hist4[j];
        hist4[j] = zero4;                              // restore invariant
        cnt += __popc(__vcmpgeu4(w.x, 0x35353535u) & 0x01010101u);
        cnt += __popc(__vcmpgeu4(w.y, 0x35353535u) & 0x01010101u);
        cnt += __popc(__vcmpgeu4(w.z, 0x35353535u) & 0x01010101u);
        cnt += __popc(__vcmpgeu4(w.w, 0x35353535u) & 0x01010101u);
    }

    // warp reduce, one atomic per warp (device atomic, no fence needed:
    // K3 observes it via the kernel-launch boundary)
    #pragma unroll
    for (int off = 16; off > 0; off >>= 1)
        cnt += __shfl_down_sync(0xFFFFFFFFu, cnt, off);
    if ((threadIdx.x & 31) == 0 && cnt)
        atomicAdd(&g_count[b], cnt);
}

// ---------------------------------------------------------------------------
// Kernel 3: expand K_b into [64, 5120, 1] and reset the counter.
// One CTA per batch; intra-block coordination only.
// ---------------------------------------------------------------------------
__global__ void dm2d_out_kernel(float* __restrict__ out) {
    const int b = blockIdx.x;
    const int K = (int)g_count[b];                     // L2 broadcast read
    float* ob = out + (size_t)b * TOPK;
    for (int i = threadIdx.x; i < TOPK; i += blockDim.x)
        ob[i] = (i < K) ? 1.0f : 0.0f;
    __syncthreads();
    if (threadIdx.x == 0) g_count[b] = 0u;             // reset for next launch
}

extern "C" void kernel_launch(void* const* d_in, const int* in_sizes, int n_in,
                              void* d_out, int out_size) {
    (void)in_sizes; (void)n_in; (void)out_size;
    const float4* pcd = reinterpret_cast<const float4*>(d_in[0]);
    float* out = reinterpret_cast<float*>(d_out);

    dim3 hgrid(64, NBATCH);
    dm2d_hist_kernel<<<hgrid, 256>>>(pcd);

    dim3 cgrid(64, NBATCH);
    dm2d_count_kernel<<<cgrid, 256>>>();

    dm2d_out_kernel<<<NBATCH, 256>>>(out);
}

// round 5
// speedup vs baseline: 2.1282x; 1.8860x over previous
#include <cuda_runtime.h>
#include <cstdint>

// DeepMapping2D occupancy_generation, GB300 sm_103a.  Round 5.
//
//   output[b] = K_b ones then zeros, K_b = #bins with count >= 53.
//   Min-shift is a bin bijection -> K_b shift-invariant -> no min pass.
//
// R4 ncu: hist is LTS-THROUGHPUT bound (issue 7.7%, L2 76.6%) -- each u8 RED
// is a 32B L2 sector RMW; ~534MB of sector traffic + 134MB input ~= the
// ~6300 B/cyc LTS cap. So: maximize outstanding REDs (full unroll), and keep
// the aux passes in their proven-fast access patterns:
//   * count pass is READ-ONLY (the R3/R4 load+store-same-line fusion was the
//     regression; ~127us vs ~12us read-only).
//   * hist zeroing is PURE STORES, fused with the (independent) output
//     expansion into one trailing kernel that prepares the next replay.
// 3 launches: hist -> count -> zero+out.

#define NBATCH  64
#define NPTS    262144
#define TOPK    5120
#define GZ_LOG2 10
#define BINS_PER_BATCH   (1024u * 1024u)          // 1M u8 bins / batch
#define HWORDS_PER_BATCH (BINS_PER_BATCH / 4)     // 256K u32 / batch

__device__ unsigned int g_hist[(size_t)NBATCH * HWORDS_PER_BATCH];  // 64 MB, load-zeroed
__device__ unsigned int g_count[NBATCH];                            // load-zeroed

// ---------------------------------------------------------------------------
// Kernel 1: histogram scatter. grid (64, 64) x 256 thr.
// Exactly 8 float4 per thread, fully unrolled: 8 front-batched LDG.128,
// then 16 independent byte-REDGs in flight per thread.
// ---------------------------------------------------------------------------
__global__ void dm2d_hist_kernel(const float4* __restrict__ pcd) {
    const int b = blockIdx.y;
    unsigned int* __restrict__ hist = g_hist + (size_t)b * HWORDS_PER_BATCH;
    const float4* __restrict__ base = pcd + (size_t)b * (NPTS / 2);

    const int tid = blockIdx.x * 256 + threadIdx.x;   // 0..16383

    float4 p[8];
    #pragma unroll
    for (int u = 0; u < 8; u++)
        p[u] = __ldcs(&base[tid + u * 16384]);        // evict-first: protect hist in L2

    #pragma unroll
    for (int u = 0; u < 8; u++) {
        // jnp.round = round-half-to-even == rintf under default RN mode.
        unsigned x0 = (unsigned)(int)rintf(1000.0f * p[u].x);
        unsigned z0 = (unsigned)(int)rintf(1000.0f * p[u].y);
        unsigned x1 = (unsigned)(int)rintf(1000.0f * p[u].z);
        unsigned z1 = (unsigned)(int)rintf(1000.0f * p[u].w);

        unsigned i0 = (x0 << GZ_LOG2) | z0;
        unsigned i1 = (x1 << GZ_LOG2) | z1;

        // fire-and-forget byte increments (return unused -> REDG)
        atomicAdd(&hist[i0 >> 2], 1u << ((i0 & 3u) << 3));
        atomicAdd(&hist[i1 >> 2], 1u << ((i1 & 3u) << 3));
    }
}

// ---------------------------------------------------------------------------
// Kernel 2: count bins >= 53 per batch. READ-ONLY over the L2-resident hist.
// grid (64, 64) x 256 thr; 4 uint4 = 64 bins per thread.
// ---------------------------------------------------------------------------
__global__ void dm2d_count_kernel() {
    const int b = blockIdx.y;
    const uint4* __restrict__ hist4 =
        reinterpret_cast<const uint4*>(g_hist + (size_t)b * HWORDS_PER_BATCH);

    const int tid = blockIdx.x * 256 + threadIdx.x;   // 0..16383

    unsigned int cnt = 0;
    #pragma unroll
    for (int u = 0; u < 4; u++) {
        uint4 w = hist4[tid + u * 16384];
        cnt += __popc(__vcmpgeu4(w.x, 0x35353535u) & 0x01010101u);
        cnt += __popc(__vcmpgeu4(w.y, 0x35353535u) & 0x01010101u);
        cnt += __popc(__vcmpgeu4(w.z, 0x35353535u) & 0x01010101u);
        cnt += __popc(__vcmpgeu4(w.w, 0x35353535u) & 0x01010101u);
    }

    #pragma unroll
    for (int off = 16; off > 0; off >>= 1)
        cnt += __shfl_down_sync(0xFFFFFFFFu, cnt, off);
    if ((threadIdx.x & 31) == 0 && cnt)
        atomicAdd(&g_count[b], cnt);
}

// ---------------------------------------------------------------------------
// Kernel 3 (fused, independent work only): pure-store re-zero of the
// histogram for the next replay + output expansion + counter reset.
// grid (64, 64) x 256 thr. The last x-CTA of each batch also writes the
// [TOPK] output slice and resets g_count[b] (intra-block ordering only).
// ---------------------------------------------------------------------------
__global__ void dm2d_zero_out_kernel(float* __restrict__ out) {
    const int b = blockIdx.y;
    uint4* __restrict__ hist4 =
        reinterpret_cast<uint4*>(g_hist + (size_t)b * HWORDS_PER_BATCH);

    const int tid = blockIdx.x * 256 + threadIdx.x;   // 0..16383
    const uint4 zero4 = make_uint4(0u, 0u, 0u, 0u);
    #pragma unroll
    for (int u = 0; u < 4; u++)
        hist4[tid + u * 16384] = zero4;               // pure stores, stay L2-dirty

    if (blockIdx.x == 63) {
        const int K = (int)g_count[b];                // written by K2 (prev launch)
        float* ob = out + (size_t)b * TOPK;
        #pragma unroll
        for (int u = 0; u < TOPK / 256; u++) {
            int i = u * 256 + threadIdx.x;
            ob[i] = (i < K) ? 1.0f : 0.0f;
        }
        __syncthreads();                              // all reads of K done
        if (threadIdx.x == 0) g_count[b] = 0u;        // reset for next replay
    }
}

extern "C" void kernel_launch(void* const* d_in, const int* in_sizes, int n_in,
                              void* d_out, int out_size) {
    (void)in_sizes; (void)n_in; (void)out_size;
    const float4* pcd = reinterpret_cast<const float4*>(d_in[0]);
    float* out = reinterpret_cast<float*>(d_out);

    dim3 grid(64, NBATCH);
    dm2d_hist_kernel<<<grid, 256>>>(pcd);
    dm2d_count_kernel<<<grid, 256>>>();
    dm2d_zero_out_kernel<<<grid, 256>>>(out);
}